// round 14
// baseline (speedup 1.0000x reference)
#include <cuda_runtime.h>
#include <cuda_bf16.h>

// Problem constants (fixed by the dataset)
#define Bn 4
#define Nn 50000
#define Dn 256
#define En 800000
#define NPTS (Bn * Nn)   // 200000
#define MAXDEG 96        // multiple of 8; Poisson(32): P(deg>88 pre-pad) ~ 1e-15

// Predict: 625 blocks x 8 warps = 5000 warps, 40 points each (exact).
// 48 regs -> 5 blocks/SM -> 625 blocks < 740 slots = ONE wave (no tail).
#define PRED_BLOCKS 625
#define PRED_WARPS  5000

// XPBD state, batch-interleaved: g_x[buf][4*n + b] = float4(x,y,z,pad).
__device__ float4 g_x[2][NPTS];

// Fixed-slot incidence table: node n owns g_slot[n*MAXDEG .. n*MAXDEG+deg).
// entry = {4*neighbor (pre-scaled float4 index), bitcast(L0)}; rows padded to
// a multiple of 8 with zero-contribution self-edges.
__device__ int  g_cnt[Nn];
__device__ int2 g_slot[Nn * MAXDEG];   // 38.4 MB

// ---------------------------------------------------------------------------
// Stage 1: x_pred = keypoints + tau * (hand_tokens @ head_w + head_b)
// Warp per point, grid-stride 40 points/warp (single wave), 2 points per
// iteration sharing one conflict-free smem weight read, software-pipelined
// (next iteration's 4 LDG.128 issued before this iteration's compute).
// ---------------------------------------------------------------------------
__global__ __launch_bounds__(256) void predict_kernel(
    const float* __restrict__ kp, const float* __restrict__ ts,
    const float* __restrict__ ht, const float* __restrict__ hw,
    const float* __restrict__ hb)
{
    __shared__ float sw[25 * 32];   // lane l's 24 weights at sw[25l..25l+23]
    __shared__ float sb[3];
    int tid = threadIdx.x;
    for (int idx = tid; idx < Dn * 3; idx += 256) {
        int r = idx / 3, c = idx - 3 * r;
        int q    = (r & 127) >> 2;                       // owner lane
        int slot = ((r >> 7) ? 12 : 0) + 3 * (r & 3) + c;
        sw[25 * q + slot] = hw[idx];
    }
    if (tid < 3) sb[tid] = hb[tid];
    __syncthreads();

    int lane = tid & 31;
    int gw   = (blockIdx.x * 256 + tid) >> 5;   // 0..4999
    const float*  wl  = &sw[25 * lane];
    const float4* ht4 = reinterpret_cast<const float4*>(ht);

    // prologue: loads for m = 0
    int p0 = gw;
    int p1 = gw + PRED_WARPS;
    float4 u0 = __ldg(&ht4[(size_t)p0 * 64 + lane]);
    float4 u1 = __ldg(&ht4[(size_t)p0 * 64 + 32 + lane]);
    float4 v0 = __ldg(&ht4[(size_t)p1 * 64 + lane]);
    float4 v1 = __ldg(&ht4[(size_t)p1 * 64 + 32 + lane]);

#pragma unroll 1
    for (int m = 0; m < 20; m++) {
        // prefetch m+1 (in flight across this iteration's compute + store)
        float4 nu0 = u0, nu1 = u1, nv0 = v0, nv1 = v1;
        if (m < 19) {
            int q0 = p0 + 2 * PRED_WARPS;
            int q1 = p1 + 2 * PRED_WARPS;
            nu0 = __ldg(&ht4[(size_t)q0 * 64 + lane]);
            nu1 = __ldg(&ht4[(size_t)q0 * 64 + 32 + lane]);
            nv0 = __ldg(&ht4[(size_t)q1 * 64 + lane]);
            nv1 = __ldg(&ht4[(size_t)q1 * 64 + 32 + lane]);
        }

        float hu[8] = {u0.x, u0.y, u0.z, u0.w, u1.x, u1.y, u1.z, u1.w};
        float hv[8] = {v0.x, v0.y, v0.z, v0.w, v1.x, v1.y, v1.z, v1.w};
        float a0 = 0.f, a1 = 0.f, a2 = 0.f;
        float b0 = 0.f, b1 = 0.f, b2 = 0.f;
#pragma unroll
        for (int i = 0; i < 8; i++) {
            float w0 = wl[3 * i + 0];   // shared by both points
            float w1 = wl[3 * i + 1];
            float w2 = wl[3 * i + 2];
            a0 = fmaf(hu[i], w0, a0); a1 = fmaf(hu[i], w1, a1); a2 = fmaf(hu[i], w2, a2);
            b0 = fmaf(hv[i], w0, b0); b1 = fmaf(hv[i], w1, b1); b2 = fmaf(hv[i], w2, b2);
        }
#pragma unroll
        for (int o = 16; o >= 1; o >>= 1) {
            a0 += __shfl_xor_sync(0xffffffffu, a0, o);
            a1 += __shfl_xor_sync(0xffffffffu, a1, o);
            a2 += __shfl_xor_sync(0xffffffffu, a2, o);
            b0 += __shfl_xor_sync(0xffffffffu, b0, o);
            b1 += __shfl_xor_sync(0xffffffffu, b1, o);
            b2 += __shfl_xor_sync(0xffffffffu, b2, o);
        }
        if (lane == 0) {
            int bi = p0 / Nn, ni = p0 - bi * Nn;
            float tau = fmaxf(1.0f - __ldg(&ts[bi]), 0.001f);
            g_x[0][4 * ni + bi] = make_float4(
                fmaf(tau, a0 + sb[0], __ldg(&kp[(size_t)p0 * 3 + 0])),
                fmaf(tau, a1 + sb[1], __ldg(&kp[(size_t)p0 * 3 + 1])),
                fmaf(tau, a2 + sb[2], __ldg(&kp[(size_t)p0 * 3 + 2])), 0.0f);
            int bj = p1 / Nn, nj = p1 - bj * Nn;
            float tau1 = fmaxf(1.0f - __ldg(&ts[bj]), 0.001f);
            g_x[0][4 * nj + bj] = make_float4(
                fmaf(tau1, b0 + sb[0], __ldg(&kp[(size_t)p1 * 3 + 0])),
                fmaf(tau1, b1 + sb[1], __ldg(&kp[(size_t)p1 * 3 + 1])),
                fmaf(tau1, b2 + sb[2], __ldg(&kp[(size_t)p1 * 3 + 2])), 0.0f);
        }

        u0 = nu0; u1 = nu1; v0 = nv0; v1 = nv1;
        p0 += 2 * PRED_WARPS; p1 += 2 * PRED_WARPS;
    }
}

// ---------------------------------------------------------------------------
// Incidence build (side stream, hidden under predict).
// ---------------------------------------------------------------------------
__global__ __launch_bounds__(256) void zero_kernel()
{
    int i = blockIdx.x * blockDim.x + threadIdx.x;
    if (i < Nn) g_cnt[i] = 0;
}

__global__ __launch_bounds__(256) void fill_kernel(
    const int* __restrict__ ei, const float* __restrict__ rest)
{
    int e = blockIdx.x * blockDim.x + threadIdx.x;
    if (e >= En) return;
    int s  = __ldg(&ei[e]);
    int d  = __ldg(&ei[En + e]);
    int L0 = __float_as_int(__ldg(&rest[e]));
    int cs = atomicAdd(&g_cnt[s], 1);
    if (cs < MAXDEG) g_slot[s * MAXDEG + cs] = make_int2(4 * d, L0);
    int cd = atomicAdd(&g_cnt[d], 1);
    if (cd < MAXDEG) g_slot[d * MAXDEG + cd] = make_int2(4 * s, L0);
}

__global__ __launch_bounds__(256) void pad_kernel()
{
    int n = blockIdx.x * blockDim.x + threadIdx.x;
    if (n >= Nn) return;
    int c = min(g_cnt[n], MAXDEG);
    int p = (c + 7) & ~7;                    // pad to multiple of 8
    int2 self = make_int2(4 * n, __float_as_int(1.0f));  // zero contribution
    for (int k = c; k < p; k++) g_slot[n * MAXDEG + k] = self;
    g_cnt[n] = p;
}

// ---------------------------------------------------------------------------
// One XPBD Jacobi iteration. TWO threads per (node,batch); half h walks
// 8-edge chunks k = 8h, 8h+16, ... Per chunk: 4 int4 entry loads then EIGHT
// independent gathers in flight (2x the MLP of the 4-edge version; dependent
// rounds per thread drop ~4 -> ~2). Layout t = 8n + 4h + b keeps batch-
// siblings' gathers in one contiguous 64B segment. Halves combined with
// shfl_xor(4); h==0 writes. If `out` != null (last iteration) h==0 emits
// v_eff = (x_new - kp)/tau. Grid exact: 400000 = 3125 x 128.
// ---------------------------------------------------------------------------
__global__ __launch_bounds__(128) void node_kernel(
    int from, int to,
    const float* __restrict__ kp, const float* __restrict__ ts,
    float* __restrict__ out)
{
    int t = blockIdx.x * 128 + threadIdx.x;
    int n = t >> 3;
    int b = t & 3;
    int h = (t >> 2) & 1;

    const float4* __restrict__ xin = g_x[from];
    float4 own = __ldg(&xin[4 * n + b]);

    int deg = __ldg(&g_cnt[n]);              // multiple of 8
    const int2* row = &g_slot[n * MAXDEG];

    float ax = 0.f, ay = 0.f, az = 0.f;

#pragma unroll 1
    for (int k = 8 * h; k < deg; k += 16) {
        int4 e0 = __ldg(reinterpret_cast<const int4*>(row + k));
        int4 e1 = __ldg(reinterpret_cast<const int4*>(row + k + 2));
        int4 e2 = __ldg(reinterpret_cast<const int4*>(row + k + 4));
        int4 e3 = __ldg(reinterpret_cast<const int4*>(row + k + 6));
        int   js[8]  = {e0.x, e0.z, e1.x, e1.z, e2.x, e2.z, e3.x, e3.z};
        float L0s[8] = {__int_as_float(e0.y), __int_as_float(e0.w),
                        __int_as_float(e1.y), __int_as_float(e1.w),
                        __int_as_float(e2.y), __int_as_float(e2.w),
                        __int_as_float(e3.y), __int_as_float(e3.w)};
        float4 xj[8];
#pragma unroll
        for (int i = 0; i < 8; i++)
            xj[i] = __ldg(&xin[js[i] + b]);      // 8 independent, in flight
#pragma unroll
        for (int i = 0; i < 8; i++) {
            float dx = own.x - xj[i].x;
            float dy = own.y - xj[i].y;
            float dz = own.z - xj[i].z;
            float d2 = fmaf(dx, dx, fmaf(dy, dy, dz * dz));
            float r  = rsqrtf(fmaxf(d2, 1e-24f));
            float f  = fmaf(L0s[i], r, -1.0f);      // 2x true scale
            ax += fminf(fmaxf(f * dx, -0.3f), 0.3f);
            ay += fminf(fmaxf(f * dy, -0.3f), 0.3f);
            az += fminf(fmaxf(f * dz, -0.3f), 0.3f);
        }
    }

    // combine the two halves (partner differs only in h -> lane xor 4)
    ax += __shfl_xor_sync(0xffffffffu, ax, 4);
    ay += __shfl_xor_sync(0xffffffffu, ay, 4);
    az += __shfl_xor_sync(0xffffffffu, az, 4);

    if (h == 0) {
        float nx = fmaf(0.5f, ax, own.x);
        float ny = fmaf(0.5f, ay, own.y);
        float nz = fmaf(0.5f, az, own.z);
        if (out == nullptr) {
            g_x[to][4 * n + b] = make_float4(nx, ny, nz, 0.0f);
        } else {
            // fused final: v_eff = (x_new - kp) / tau
            float inv_tau = 1.0f / fmaxf(1.0f - __ldg(&ts[b]), 0.001f);
            size_t o = (size_t)(b * Nn + n) * 3;
            out[o + 0] = (nx - __ldg(&kp[o + 0])) * inv_tau;
            out[o + 1] = (ny - __ldg(&kp[o + 1])) * inv_tau;
            out[o + 2] = (nz - __ldg(&kp[o + 2])) * inv_tau;
        }
    }
}

extern "C" void kernel_launch(void* const* d_in, const int* in_sizes, int n_in,
                              void* d_out, int out_size)
{
    const float* kp   = (const float*)d_in[0];  // keypoints   (B,N,3)
    const float* ts   = (const float*)d_in[1];  // timesteps   (B,)
    const float* ht   = (const float*)d_in[2];  // hand_tokens (B,N,D)
    const float* hw   = (const float*)d_in[3];  // head_w      (D,3)
    const float* hb   = (const float*)d_in[4];  // head_b      (3,)
    const int*   ei   = (const int*)  d_in[5];  // edge_index  (2,E)
    const float* rest = (const float*)d_in[6];  // rest_lengths(E,)
    float*       out  = (float*)d_out;          // v_eff       (B,N,3)

    (void)in_sizes; (void)n_in; (void)out_size;

    // Side stream + fork/join events, created once on the first (uncaptured)
    // correctness call. Host-side objects only.
    static cudaStream_t side = nullptr;
    static cudaEvent_t  ev_fork = nullptr, ev_join = nullptr;
    if (side == nullptr) {
        cudaStreamCreateWithFlags(&side, cudaStreamNonBlocking);
        cudaEventCreateWithFlags(&ev_fork, cudaEventDisableTiming);
        cudaEventCreateWithFlags(&ev_join, cudaEventDisableTiming);
    }

    const int nb_nodes = (Nn + 255) / 256;
    const int nb_edges = (En + 255) / 256;
    const int nb_node2 = (2 * NPTS) / 128;     // 3125, exact

    // Fork: incidence build on side stream, concurrent with predict.
    cudaEventRecord(ev_fork, 0);
    cudaStreamWaitEvent(side, ev_fork, 0);
    zero_kernel<<<nb_nodes, 256, 0, side>>>();
    fill_kernel<<<nb_edges, 256, 0, side>>>(ei, rest);
    pad_kernel <<<nb_nodes, 256, 0, side>>>();

    // Stage 1 on the main stream, overlapping the build
    predict_kernel<<<PRED_BLOCKS, 256>>>(kp, ts, ht, hw, hb);

    // Join
    cudaEventRecord(ev_join, side);
    cudaStreamWaitEvent(0, ev_join, 0);

    // Stage 2: 4 Jacobi XPBD iterations; the 4th fuses the velocity output
    node_kernel<<<nb_node2, 128>>>(0, 1, kp, ts, nullptr);
    node_kernel<<<nb_node2, 128>>>(1, 0, kp, ts, nullptr);
    node_kernel<<<nb_node2, 128>>>(0, 1, kp, ts, nullptr);
    node_kernel<<<nb_node2, 128>>>(1, 0, kp, ts, out);
}

// round 16
// speedup vs baseline: 1.0300x; 1.0300x over previous
#include <cuda_runtime.h>
#include <cuda_bf16.h>

// Problem constants (fixed by the dataset)
#define Bn 4
#define Nn 50000
#define Dn 256
#define En 800000
#define NPTS (Bn * Nn)   // 200000
#define MAXDEG 96        // Poisson(32): P(deg>96) ~ 1e-18 over 50k nodes

// Predict: 1250 blocks x 8 warps = 10000 warps, 20 points each (exact)
#define PRED_BLOCKS 1250
#define PRED_WARPS  10000

// XPBD state, batch-interleaved: g_x[buf][4*n + b] = float4(x,y,z,pad).
__device__ float4 g_x[2][NPTS];

// Fixed-slot incidence table: node n owns g_slot[n*MAXDEG .. n*MAXDEG+deg).
// entry = {4*neighbor (pre-scaled float4 index), bitcast(L0)}; rows padded to
// a multiple of 4 with zero-contribution self-edges.
__device__ int  g_cnt[Nn];
__device__ int2 g_slot[Nn * MAXDEG];   // 38.4 MB

// ---------------------------------------------------------------------------
// Stage 1: x_pred = keypoints + tau * (hand_tokens @ head_w + head_b)
// Warp per point, grid-stride 20 points/warp, 2 points per iteration sharing
// one conflict-free smem weight read. DEPTH-2 software pipeline: loads for
// m+1 AND m+2 in flight while computing m -> 8 LDG.128 outstanding per warp.
// R15 bug fixed: prefetch targets iteration m+2, so the guard is m < 8
// (m+2 <= 9); indices additionally clamped to the valid range.
// ---------------------------------------------------------------------------
__global__ __launch_bounds__(256) void predict_kernel(
    const float* __restrict__ kp, const float* __restrict__ ts,
    const float* __restrict__ ht, const float* __restrict__ hw,
    const float* __restrict__ hb)
{
    __shared__ float sw[25 * 32];   // lane l's 24 weights at sw[25l..25l+23]
    __shared__ float sb[3];
    int tid = threadIdx.x;
    for (int idx = tid; idx < Dn * 3; idx += 256) {
        int r = idx / 3, c = idx - 3 * r;
        int q    = (r & 127) >> 2;                       // owner lane
        int slot = ((r >> 7) ? 12 : 0) + 3 * (r & 3) + c;
        sw[25 * q + slot] = hw[idx];
    }
    if (tid < 3) sb[tid] = hb[tid];
    __syncthreads();

    int lane = tid & 31;
    int gw   = (blockIdx.x * 256 + tid) >> 5;   // 0..9999
    const float*  wl  = &sw[25 * lane];
    const float4* ht4 = reinterpret_cast<const float4*>(ht);

    // prologue: loads for m = 0 (A) and m = 1 (B)
    int pa0 = gw, pa1 = gw + PRED_WARPS;
    float4 Au0 = __ldg(&ht4[(size_t)pa0 * 64 + lane]);
    float4 Au1 = __ldg(&ht4[(size_t)pa0 * 64 + 32 + lane]);
    float4 Av0 = __ldg(&ht4[(size_t)pa1 * 64 + lane]);
    float4 Av1 = __ldg(&ht4[(size_t)pa1 * 64 + 32 + lane]);
    int pb0 = pa0 + 2 * PRED_WARPS, pb1 = pa1 + 2 * PRED_WARPS;
    float4 Bu0 = __ldg(&ht4[(size_t)pb0 * 64 + lane]);
    float4 Bu1 = __ldg(&ht4[(size_t)pb0 * 64 + 32 + lane]);
    float4 Bv0 = __ldg(&ht4[(size_t)pb1 * 64 + lane]);
    float4 Bv1 = __ldg(&ht4[(size_t)pb1 * 64 + 32 + lane]);

#pragma unroll 2
    for (int m = 0; m < 10; m++) {
        // issue loads for m+2 (valid only while m+2 <= 9, i.e. m < 8)
        float4 Cu0 = Bu0, Cu1 = Bu1, Cv0 = Bv0, Cv1 = Bv1;
        if (m < 8) {
            int qc0 = min(pa0 + 4 * PRED_WARPS, NPTS - 1);   // clamp (safety)
            int qc1 = min(pa1 + 4 * PRED_WARPS, NPTS - 1);
            Cu0 = __ldg(&ht4[(size_t)qc0 * 64 + lane]);
            Cu1 = __ldg(&ht4[(size_t)qc0 * 64 + 32 + lane]);
            Cv0 = __ldg(&ht4[(size_t)qc1 * 64 + lane]);
            Cv1 = __ldg(&ht4[(size_t)qc1 * 64 + 32 + lane]);
        }

        float hu[8] = {Au0.x, Au0.y, Au0.z, Au0.w, Au1.x, Au1.y, Au1.z, Au1.w};
        float hv[8] = {Av0.x, Av0.y, Av0.z, Av0.w, Av1.x, Av1.y, Av1.z, Av1.w};
        float a0 = 0.f, a1 = 0.f, a2 = 0.f;
        float b0 = 0.f, b1 = 0.f, b2 = 0.f;
#pragma unroll
        for (int i = 0; i < 8; i++) {
            float w0 = wl[3 * i + 0];   // shared by both points
            float w1 = wl[3 * i + 1];
            float w2 = wl[3 * i + 2];
            a0 = fmaf(hu[i], w0, a0); a1 = fmaf(hu[i], w1, a1); a2 = fmaf(hu[i], w2, a2);
            b0 = fmaf(hv[i], w0, b0); b1 = fmaf(hv[i], w1, b1); b2 = fmaf(hv[i], w2, b2);
        }
#pragma unroll
        for (int o = 16; o >= 1; o >>= 1) {
            a0 += __shfl_xor_sync(0xffffffffu, a0, o);
            a1 += __shfl_xor_sync(0xffffffffu, a1, o);
            a2 += __shfl_xor_sync(0xffffffffu, a2, o);
            b0 += __shfl_xor_sync(0xffffffffu, b0, o);
            b1 += __shfl_xor_sync(0xffffffffu, b1, o);
            b2 += __shfl_xor_sync(0xffffffffu, b2, o);
        }
        if (lane == 0) {
            int bi = pa0 / Nn, ni = pa0 - bi * Nn;
            float tau = fmaxf(1.0f - __ldg(&ts[bi]), 0.001f);
            g_x[0][4 * ni + bi] = make_float4(
                fmaf(tau, a0 + sb[0], __ldg(&kp[(size_t)pa0 * 3 + 0])),
                fmaf(tau, a1 + sb[1], __ldg(&kp[(size_t)pa0 * 3 + 1])),
                fmaf(tau, a2 + sb[2], __ldg(&kp[(size_t)pa0 * 3 + 2])), 0.0f);
            int bj = pa1 / Nn, nj = pa1 - bj * Nn;
            float tau1 = fmaxf(1.0f - __ldg(&ts[bj]), 0.001f);
            g_x[0][4 * nj + bj] = make_float4(
                fmaf(tau1, b0 + sb[0], __ldg(&kp[(size_t)pa1 * 3 + 0])),
                fmaf(tau1, b1 + sb[1], __ldg(&kp[(size_t)pa1 * 3 + 1])),
                fmaf(tau1, b2 + sb[2], __ldg(&kp[(size_t)pa1 * 3 + 2])), 0.0f);
        }

        // rotate pipeline registers (free after unroll-2)
        Au0 = Bu0; Au1 = Bu1; Av0 = Bv0; Av1 = Bv1;
        Bu0 = Cu0; Bu1 = Cu1; Bv0 = Cv0; Bv1 = Cv1;
        pa0 += 2 * PRED_WARPS; pa1 += 2 * PRED_WARPS;
    }
}

// ---------------------------------------------------------------------------
// Incidence build (side stream, hidden under predict).
// ---------------------------------------------------------------------------
__global__ __launch_bounds__(256) void zero_kernel()
{
    int i = blockIdx.x * blockDim.x + threadIdx.x;
    if (i < Nn) g_cnt[i] = 0;
}

__global__ __launch_bounds__(256) void fill_kernel(
    const int* __restrict__ ei, const float* __restrict__ rest)
{
    int e = blockIdx.x * blockDim.x + threadIdx.x;
    if (e >= En) return;
    int s  = __ldg(&ei[e]);
    int d  = __ldg(&ei[En + e]);
    int L0 = __float_as_int(__ldg(&rest[e]));
    int cs = atomicAdd(&g_cnt[s], 1);
    if (cs < MAXDEG) g_slot[s * MAXDEG + cs] = make_int2(4 * d, L0);
    int cd = atomicAdd(&g_cnt[d], 1);
    if (cd < MAXDEG) g_slot[d * MAXDEG + cd] = make_int2(4 * s, L0);
}

__global__ __launch_bounds__(256) void pad_kernel()
{
    int n = blockIdx.x * blockDim.x + threadIdx.x;
    if (n >= Nn) return;
    int c = min(g_cnt[n], MAXDEG);
    int p = (c + 3) & ~3;                    // pad to multiple of 4
    int2 self = make_int2(4 * n, __float_as_int(1.0f));  // zero contribution
    for (int k = c; k < p; k++) g_slot[n * MAXDEG + k] = self;
    g_cnt[n] = p;
}

// ---------------------------------------------------------------------------
// One XPBD Jacobi iteration (R13 config — measured best): TWO threads per
// (node,batch), half h walks groups k = 4h, 4h+8, ... with next-group entry
// prefetch. Layout t = 8n + 4h + b. Halves combined with shfl_xor(4).
// If `out` != null (last iteration) h==0 emits v_eff = (x_new - kp)/tau.
// Grid exact: 400000 = 3125 x 128.
// ---------------------------------------------------------------------------
__global__ __launch_bounds__(128) void node_kernel(
    int from, int to,
    const float* __restrict__ kp, const float* __restrict__ ts,
    float* __restrict__ out)
{
    int t = blockIdx.x * 128 + threadIdx.x;
    int n = t >> 3;
    int b = t & 3;
    int h = (t >> 2) & 1;

    const float4* __restrict__ xin = g_x[from];
    float4 own = __ldg(&xin[4 * n + b]);

    int deg = __ldg(&g_cnt[n]);              // multiple of 4
    const int2* row = &g_slot[n * MAXDEG];

    float ax = 0.f, ay = 0.f, az = 0.f;

    int k = 4 * h;
    if (k < deg) {
        int4 ea = __ldg(reinterpret_cast<const int4*>(row + k));
        int4 eb = __ldg(reinterpret_cast<const int4*>(row + k + 2));
        while (true) {
            int kn = k + 8;
            int4 na, nb;
            bool more = (kn < deg);
            if (more) {                      // prefetch next group's entries
                na = __ldg(reinterpret_cast<const int4*>(row + kn));
                nb = __ldg(reinterpret_cast<const int4*>(row + kn + 2));
            }
            int   js[4]  = {ea.x, ea.z, eb.x, eb.z};    // already 4*j
            float L0s[4] = {__int_as_float(ea.y), __int_as_float(ea.w),
                            __int_as_float(eb.y), __int_as_float(eb.w)};
            float4 xj[4];
#pragma unroll
            for (int i = 0; i < 4; i++)
                xj[i] = __ldg(&xin[js[i] + b]);
#pragma unroll
            for (int i = 0; i < 4; i++) {
                float dx = own.x - xj[i].x;
                float dy = own.y - xj[i].y;
                float dz = own.z - xj[i].z;
                float d2 = fmaf(dx, dx, fmaf(dy, dy, dz * dz));
                float r  = rsqrtf(fmaxf(d2, 1e-24f));
                float f  = fmaf(L0s[i], r, -1.0f);      // 2x true scale
                ax += fminf(fmaxf(f * dx, -0.3f), 0.3f);
                ay += fminf(fmaxf(f * dy, -0.3f), 0.3f);
                az += fminf(fmaxf(f * dz, -0.3f), 0.3f);
            }
            if (!more) break;
            ea = na; eb = nb; k = kn;
        }
    }

    // combine the two halves (partner differs only in h -> lane xor 4)
    ax += __shfl_xor_sync(0xffffffffu, ax, 4);
    ay += __shfl_xor_sync(0xffffffffu, ay, 4);
    az += __shfl_xor_sync(0xffffffffu, az, 4);

    if (h == 0) {
        float nx = fmaf(0.5f, ax, own.x);
        float ny = fmaf(0.5f, ay, own.y);
        float nz = fmaf(0.5f, az, own.z);
        if (out == nullptr) {
            g_x[to][4 * n + b] = make_float4(nx, ny, nz, 0.0f);
        } else {
            // fused final: v_eff = (x_new - kp) / tau
            float inv_tau = 1.0f / fmaxf(1.0f - __ldg(&ts[b]), 0.001f);
            size_t o = (size_t)(b * Nn + n) * 3;
            out[o + 0] = (nx - __ldg(&kp[o + 0])) * inv_tau;
            out[o + 1] = (ny - __ldg(&kp[o + 1])) * inv_tau;
            out[o + 2] = (nz - __ldg(&kp[o + 2])) * inv_tau;
        }
    }
}

extern "C" void kernel_launch(void* const* d_in, const int* in_sizes, int n_in,
                              void* d_out, int out_size)
{
    const float* kp   = (const float*)d_in[0];  // keypoints   (B,N,3)
    const float* ts   = (const float*)d_in[1];  // timesteps   (B,)
    const float* ht   = (const float*)d_in[2];  // hand_tokens (B,N,D)
    const float* hw   = (const float*)d_in[3];  // head_w      (D,3)
    const float* hb   = (const float*)d_in[4];  // head_b      (3,)
    const int*   ei   = (const int*)  d_in[5];  // edge_index  (2,E)
    const float* rest = (const float*)d_in[6];  // rest_lengths(E,)
    float*       out  = (float*)d_out;          // v_eff       (B,N,3)

    (void)in_sizes; (void)n_in; (void)out_size;

    // Side stream + fork/join events, created once on the first (uncaptured)
    // correctness call. Host-side objects only.
    static cudaStream_t side = nullptr;
    static cudaEvent_t  ev_fork = nullptr, ev_join = nullptr;
    if (side == nullptr) {
        cudaStreamCreateWithFlags(&side, cudaStreamNonBlocking);
        cudaEventCreateWithFlags(&ev_fork, cudaEventDisableTiming);
        cudaEventCreateWithFlags(&ev_join, cudaEventDisableTiming);
    }

    const int nb_nodes = (Nn + 255) / 256;
    const int nb_edges = (En + 255) / 256;
    const int nb_node2 = (2 * NPTS) / 128;     // 3125, exact

    // Fork: incidence build on side stream, concurrent with predict.
    cudaEventRecord(ev_fork, 0);
    cudaStreamWaitEvent(side, ev_fork, 0);
    zero_kernel<<<nb_nodes, 256, 0, side>>>();
    fill_kernel<<<nb_edges, 256, 0, side>>>(ei, rest);
    pad_kernel <<<nb_nodes, 256, 0, side>>>();

    // Stage 1 on the main stream, overlapping the build
    predict_kernel<<<PRED_BLOCKS, 256>>>(kp, ts, ht, hw, hb);

    // Join
    cudaEventRecord(ev_join, side);
    cudaStreamWaitEvent(0, ev_join, 0);

    // Stage 2: 4 Jacobi XPBD iterations; the 4th fuses the velocity output
    node_kernel<<<nb_node2, 128>>>(0, 1, kp, ts, nullptr);
    node_kernel<<<nb_node2, 128>>>(1, 0, kp, ts, nullptr);
    node_kernel<<<nb_node2, 128>>>(0, 1, kp, ts, nullptr);
    node_kernel<<<nb_node2, 128>>>(1, 0, kp, ts, out);
}

// round 17
// speedup vs baseline: 1.0745x; 1.0432x over previous
#include <cuda_runtime.h>
#include <cuda_bf16.h>

// Problem constants (fixed by the dataset)
#define Bn 4
#define Nn 50000
#define Dn 256
#define En 800000
#define NPTS (Bn * Nn)   // 200000
#define MAXDEG 96        // Poisson(32): P(deg>96) ~ 1e-18 over 50k nodes

// Predict: 1250 blocks x 8 warps = 10000 warps, 20 points each (exact)
#define PRED_BLOCKS 1250
#define PRED_WARPS  10000

// XPBD state, batch-interleaved: g_x[buf][4*n + b] = float4(x,y,z,pad).
__device__ float4 g_x[2][NPTS];

// Fixed-slot incidence table: node n owns g_slot[n*MAXDEG .. n*MAXDEG+deg).
// entry = {4*neighbor (pre-scaled float4 index), bitcast(L0)}; rows padded to
// a multiple of 4 with zero-contribution self-edges.
__device__ int  g_cnt[Nn];
__device__ int2 g_slot[Nn * MAXDEG];   // 38.4 MB

// ---------------------------------------------------------------------------
// Stage 1: x_pred = keypoints + tau * (hand_tokens @ head_w + head_b)
// R13 structure (depth-1 pipeline, 48 regs, 1250 blocks — measured optimum)
// with a TWO-TREE reduction: one xor-16 round on all 6 accumulators, merge
// (lanes 0-15 carry point-A partials, 16-31 point-B partials), then a single
// 4-round butterfly on 3 values. 30 -> 21 shfl per iteration, and the
// epilogue stores run on lanes 0 and 16 in parallel.
// ---------------------------------------------------------------------------
__global__ __launch_bounds__(256) void predict_kernel(
    const float* __restrict__ kp, const float* __restrict__ ts,
    const float* __restrict__ ht, const float* __restrict__ hw,
    const float* __restrict__ hb)
{
    __shared__ float sw[25 * 32];   // lane l's 24 weights at sw[25l..25l+23]
    __shared__ float sb[3];
    int tid = threadIdx.x;
    for (int idx = tid; idx < Dn * 3; idx += 256) {
        int r = idx / 3, c = idx - 3 * r;
        int q    = (r & 127) >> 2;                       // owner lane
        int slot = ((r >> 7) ? 12 : 0) + 3 * (r & 3) + c;
        sw[25 * q + slot] = hw[idx];
    }
    if (tid < 3) sb[tid] = hb[tid];
    __syncthreads();

    int lane = tid & 31;
    int gw   = (blockIdx.x * 256 + tid) >> 5;   // 0..9999
    const float*  wl  = &sw[25 * lane];
    const float4* ht4 = reinterpret_cast<const float4*>(ht);

    // prologue: loads for m = 0
    int p0 = gw;
    int p1 = gw + PRED_WARPS;
    float4 u0 = __ldg(&ht4[(size_t)p0 * 64 + lane]);
    float4 u1 = __ldg(&ht4[(size_t)p0 * 64 + 32 + lane]);
    float4 v0 = __ldg(&ht4[(size_t)p1 * 64 + lane]);
    float4 v1 = __ldg(&ht4[(size_t)p1 * 64 + 32 + lane]);

#pragma unroll 1
    for (int m = 0; m < 10; m++) {
        // prefetch m+1 (in flight across this iteration's compute + store)
        float4 nu0 = u0, nu1 = u1, nv0 = v0, nv1 = v1;
        if (m < 9) {
            int q0 = p0 + 2 * PRED_WARPS;
            int q1 = p1 + 2 * PRED_WARPS;
            nu0 = __ldg(&ht4[(size_t)q0 * 64 + lane]);
            nu1 = __ldg(&ht4[(size_t)q0 * 64 + 32 + lane]);
            nv0 = __ldg(&ht4[(size_t)q1 * 64 + lane]);
            nv1 = __ldg(&ht4[(size_t)q1 * 64 + 32 + lane]);
        }

        float hu[8] = {u0.x, u0.y, u0.z, u0.w, u1.x, u1.y, u1.z, u1.w};
        float hv[8] = {v0.x, v0.y, v0.z, v0.w, v1.x, v1.y, v1.z, v1.w};
        float a0 = 0.f, a1 = 0.f, a2 = 0.f;
        float b0 = 0.f, b1 = 0.f, b2 = 0.f;
#pragma unroll
        for (int i = 0; i < 8; i++) {
            float w0 = wl[3 * i + 0];   // shared by both points
            float w1 = wl[3 * i + 1];
            float w2 = wl[3 * i + 2];
            a0 = fmaf(hu[i], w0, a0); a1 = fmaf(hu[i], w1, a1); a2 = fmaf(hu[i], w2, a2);
            b0 = fmaf(hv[i], w0, b0); b1 = fmaf(hv[i], w1, b1); b2 = fmaf(hv[i], w2, b2);
        }

        // two-tree reduction: xor-16 on all six, merge, 4-round butterfly on 3
        a0 += __shfl_xor_sync(0xffffffffu, a0, 16);
        a1 += __shfl_xor_sync(0xffffffffu, a1, 16);
        a2 += __shfl_xor_sync(0xffffffffu, a2, 16);
        b0 += __shfl_xor_sync(0xffffffffu, b0, 16);
        b1 += __shfl_xor_sync(0xffffffffu, b1, 16);
        b2 += __shfl_xor_sync(0xffffffffu, b2, 16);
        // lanes 0-15: A partials; lanes 16-31: B partials (complete sets)
        float x0 = (lane < 16) ? a0 : b0;
        float x1 = (lane < 16) ? a1 : b1;
        float x2 = (lane < 16) ? a2 : b2;
#pragma unroll
        for (int o = 8; o >= 1; o >>= 1) {
            x0 += __shfl_xor_sync(0xffffffffu, x0, o);
            x1 += __shfl_xor_sync(0xffffffffu, x1, o);
            x2 += __shfl_xor_sync(0xffffffffu, x2, o);
        }
        // lane 0 holds totals for p0, lane 16 holds totals for p1
        if ((lane & 15) == 0) {
            int p = (lane < 16) ? p0 : p1;
            int bi = p / Nn, ni = p - bi * Nn;
            float tau = fmaxf(1.0f - __ldg(&ts[bi]), 0.001f);
            g_x[0][4 * ni + bi] = make_float4(
                fmaf(tau, x0 + sb[0], __ldg(&kp[(size_t)p * 3 + 0])),
                fmaf(tau, x1 + sb[1], __ldg(&kp[(size_t)p * 3 + 1])),
                fmaf(tau, x2 + sb[2], __ldg(&kp[(size_t)p * 3 + 2])), 0.0f);
        }

        u0 = nu0; u1 = nu1; v0 = nv0; v1 = nv1;
        p0 += 2 * PRED_WARPS; p1 += 2 * PRED_WARPS;
    }
}

// ---------------------------------------------------------------------------
// Incidence build (side stream, hidden under predict).
// ---------------------------------------------------------------------------
__global__ __launch_bounds__(256) void zero_kernel()
{
    int i = blockIdx.x * blockDim.x + threadIdx.x;
    if (i < Nn) g_cnt[i] = 0;
}

__global__ __launch_bounds__(256) void fill_kernel(
    const int* __restrict__ ei, const float* __restrict__ rest)
{
    int e = blockIdx.x * blockDim.x + threadIdx.x;
    if (e >= En) return;
    int s  = __ldg(&ei[e]);
    int d  = __ldg(&ei[En + e]);
    int L0 = __float_as_int(__ldg(&rest[e]));
    int cs = atomicAdd(&g_cnt[s], 1);
    if (cs < MAXDEG) g_slot[s * MAXDEG + cs] = make_int2(4 * d, L0);
    int cd = atomicAdd(&g_cnt[d], 1);
    if (cd < MAXDEG) g_slot[d * MAXDEG + cd] = make_int2(4 * s, L0);
}

__global__ __launch_bounds__(256) void pad_kernel()
{
    int n = blockIdx.x * blockDim.x + threadIdx.x;
    if (n >= Nn) return;
    int c = min(g_cnt[n], MAXDEG);
    int p = (c + 3) & ~3;                    // pad to multiple of 4
    int2 self = make_int2(4 * n, __float_as_int(1.0f));  // zero contribution
    for (int k = c; k < p; k++) g_slot[n * MAXDEG + k] = self;
    g_cnt[n] = p;
}

// ---------------------------------------------------------------------------
// One XPBD Jacobi iteration (R13 config — measured best): TWO threads per
// (node,batch), half h walks groups k = 4h, 4h+8, ... with next-group entry
// prefetch. Layout t = 8n + 4h + b. Halves combined with shfl_xor(4).
// If `out` != null (last iteration) h==0 emits v_eff = (x_new - kp)/tau.
// Grid exact: 400000 = 3125 x 128.
// ---------------------------------------------------------------------------
__global__ __launch_bounds__(128) void node_kernel(
    int from, int to,
    const float* __restrict__ kp, const float* __restrict__ ts,
    float* __restrict__ out)
{
    int t = blockIdx.x * 128 + threadIdx.x;
    int n = t >> 3;
    int b = t & 3;
    int h = (t >> 2) & 1;

    const float4* __restrict__ xin = g_x[from];
    float4 own = __ldg(&xin[4 * n + b]);

    int deg = __ldg(&g_cnt[n]);              // multiple of 4
    const int2* row = &g_slot[n * MAXDEG];

    float ax = 0.f, ay = 0.f, az = 0.f;

    int k = 4 * h;
    if (k < deg) {
        int4 ea = __ldg(reinterpret_cast<const int4*>(row + k));
        int4 eb = __ldg(reinterpret_cast<const int4*>(row + k + 2));
        while (true) {
            int kn = k + 8;
            int4 na, nb;
            bool more = (kn < deg);
            if (more) {                      // prefetch next group's entries
                na = __ldg(reinterpret_cast<const int4*>(row + kn));
                nb = __ldg(reinterpret_cast<const int4*>(row + kn + 2));
            }
            int   js[4]  = {ea.x, ea.z, eb.x, eb.z};    // already 4*j
            float L0s[4] = {__int_as_float(ea.y), __int_as_float(ea.w),
                            __int_as_float(eb.y), __int_as_float(eb.w)};
            float4 xj[4];
#pragma unroll
            for (int i = 0; i < 4; i++)
                xj[i] = __ldg(&xin[js[i] + b]);
#pragma unroll
            for (int i = 0; i < 4; i++) {
                float dx = own.x - xj[i].x;
                float dy = own.y - xj[i].y;
                float dz = own.z - xj[i].z;
                float d2 = fmaf(dx, dx, fmaf(dy, dy, dz * dz));
                float r  = rsqrtf(fmaxf(d2, 1e-24f));
                float f  = fmaf(L0s[i], r, -1.0f);      // 2x true scale
                ax += fminf(fmaxf(f * dx, -0.3f), 0.3f);
                ay += fminf(fmaxf(f * dy, -0.3f), 0.3f);
                az += fminf(fmaxf(f * dz, -0.3f), 0.3f);
            }
            if (!more) break;
            ea = na; eb = nb; k = kn;
        }
    }

    // combine the two halves (partner differs only in h -> lane xor 4)
    ax += __shfl_xor_sync(0xffffffffu, ax, 4);
    ay += __shfl_xor_sync(0xffffffffu, ay, 4);
    az += __shfl_xor_sync(0xffffffffu, az, 4);

    if (h == 0) {
        float nx = fmaf(0.5f, ax, own.x);
        float ny = fmaf(0.5f, ay, own.y);
        float nz = fmaf(0.5f, az, own.z);
        if (out == nullptr) {
            g_x[to][4 * n + b] = make_float4(nx, ny, nz, 0.0f);
        } else {
            // fused final: v_eff = (x_new - kp) / tau
            float inv_tau = 1.0f / fmaxf(1.0f - __ldg(&ts[b]), 0.001f);
            size_t o = (size_t)(b * Nn + n) * 3;
            out[o + 0] = (nx - __ldg(&kp[o + 0])) * inv_tau;
            out[o + 1] = (ny - __ldg(&kp[o + 1])) * inv_tau;
            out[o + 2] = (nz - __ldg(&kp[o + 2])) * inv_tau;
        }
    }
}

extern "C" void kernel_launch(void* const* d_in, const int* in_sizes, int n_in,
                              void* d_out, int out_size)
{
    const float* kp   = (const float*)d_in[0];  // keypoints   (B,N,3)
    const float* ts   = (const float*)d_in[1];  // timesteps   (B,)
    const float* ht   = (const float*)d_in[2];  // hand_tokens (B,N,D)
    const float* hw   = (const float*)d_in[3];  // head_w      (D,3)
    const float* hb   = (const float*)d_in[4];  // head_b      (3,)
    const int*   ei   = (const int*)  d_in[5];  // edge_index  (2,E)
    const float* rest = (const float*)d_in[6];  // rest_lengths(E,)
    float*       out  = (float*)d_out;          // v_eff       (B,N,3)

    (void)in_sizes; (void)n_in; (void)out_size;

    // Side stream + fork/join events, created once on the first (uncaptured)
    // correctness call. Host-side objects only.
    static cudaStream_t side = nullptr;
    static cudaEvent_t  ev_fork = nullptr, ev_join = nullptr;
    if (side == nullptr) {
        cudaStreamCreateWithFlags(&side, cudaStreamNonBlocking);
        cudaEventCreateWithFlags(&ev_fork, cudaEventDisableTiming);
        cudaEventCreateWithFlags(&ev_join, cudaEventDisableTiming);
    }

    const int nb_nodes = (Nn + 255) / 256;
    const int nb_edges = (En + 255) / 256;
    const int nb_node2 = (2 * NPTS) / 128;     // 3125, exact

    // Fork: incidence build on side stream, concurrent with predict.
    cudaEventRecord(ev_fork, 0);
    cudaStreamWaitEvent(side, ev_fork, 0);
    zero_kernel<<<nb_nodes, 256, 0, side>>>();
    fill_kernel<<<nb_edges, 256, 0, side>>>(ei, rest);
    pad_kernel <<<nb_nodes, 256, 0, side>>>();

    // Stage 1 on the main stream, overlapping the build
    predict_kernel<<<PRED_BLOCKS, 256>>>(kp, ts, ht, hw, hb);

    // Join
    cudaEventRecord(ev_join, side);
    cudaStreamWaitEvent(0, ev_join, 0);

    // Stage 2: 4 Jacobi XPBD iterations; the 4th fuses the velocity output
    node_kernel<<<nb_node2, 128>>>(0, 1, kp, ts, nullptr);
    node_kernel<<<nb_node2, 128>>>(1, 0, kp, ts, nullptr);
    node_kernel<<<nb_node2, 128>>>(0, 1, kp, ts, nullptr);
    node_kernel<<<nb_node2, 128>>>(1, 0, kp, ts, out);
}